// round 11
// baseline (speedup 1.0000x reference)
#include <cuda_runtime.h>

// FINAL — Prod_cmp: complex multiply + [reals | imags] repack. B=256, N=65536.
// in:  I1, I2 as (B, N, 2) fp32 interleaved complex
// out: (B, 2N) fp32 where out[b, 0..N) = real[b,:], out[b, N..2N) = imag[b,:]
//
// HBM-bound at the chip's mixed-stream ceiling: 402 MB mandatory traffic
// (268 R : 134 W, zero reuse) at ~6.76 TB/s = 84.5% of spec, 52.0us kernel.
// Best measured configuration: 512-thread blocks (8192 CTAs), warp-coalesced
// 512B-contiguous LDG.128 (every 32B sector fetched exactly once), __stcs
// coalesced STG.64 stores. Exhausted-and-worse/neutral: load cache hints,
// 8/thread coarsening, persistent CTAs, 32B aggregate loads, strided loads,
// 256-thread blocks.

static constexpr int B_DIM = 256;
static constexpr int N_DIM = 65536;            // complex per row
static constexpr int N_SHIFT = 16;             // log2(N_DIM)
static constexpr unsigned N_MASK = N_DIM - 1;

static constexpr int THREADS = 512;

__global__ void __launch_bounds__(THREADS, 4)
prod_cmp_kernel(const float4* __restrict__ in1,
                const float4* __restrict__ in2,
                float2* __restrict__ out)
{
    const int lane = threadIdx.x & 31;
    const long long gwarp =
        (((long long)blockIdx.x * blockDim.x + threadIdx.x) >> 5);
    const long long warpbase = gwarp * 64;     // first input float4 of this warp
    const long long j0 = warpbase + lane;      // warp-contiguous
    const long long j1 = j0 + 32;              // warp-contiguous

    // Fully coalesced 512B-per-warp loads (each 32B sector fetched once)
    const float4 a0 = in1[j0];
    const float4 a1 = in1[j1];
    const float4 c0 = in2[j0];
    const float4 c1 = in2[j1];

    // float4 j holds complex elements 2j and 2j+1
    const long long cc0 = j0 * 2;                    // first complex of a0
    const unsigned b  = (unsigned)(cc0 >> N_SHIFT);  // row (uniform per warp)
    const unsigned k0 = (unsigned)(cc0 & N_MASK);    // in-row pos of a0 (even)
    const unsigned k1 = k0 + 64;                     // in-row pos of a1 (same row)

    float2 re0, im0, re1, im1;
    re0.x = fmaf(a0.x, c0.x, -a0.y * c0.y);
    im0.x = fmaf(a0.y, c0.x,  a0.x * c0.y);
    re0.y = fmaf(a0.z, c0.z, -a0.w * c0.w);
    im0.y = fmaf(a0.w, c0.z,  a0.z * c0.w);
    re1.x = fmaf(a1.x, c1.x, -a1.y * c1.y);
    im1.x = fmaf(a1.y, c1.x,  a1.x * c1.y);
    re1.y = fmaf(a1.z, c1.z, -a1.w * c1.w);
    im1.y = fmaf(a1.w, c1.z,  a1.z * c1.w);

    // Output row b: 2N floats. As float2 indices:
    //   reals: b*N + k/2,  imags: b*N + N/2 + k/2
    const long long row_f2 = (long long)b * N_DIM;
    __stcs(&out[row_f2 + (k0 >> 1)], re0);
    __stcs(&out[row_f2 + (k1 >> 1)], re1);
    __stcs(&out[row_f2 + (N_DIM >> 1) + (k0 >> 1)], im0);
    __stcs(&out[row_f2 + (N_DIM >> 1) + (k1 >> 1)], im1);
}

extern "C" void kernel_launch(void* const* d_in, const int* in_sizes, int n_in,
                              void* d_out, int out_size)
{
    const float4* in1 = (const float4*)d_in[0];
    const float4* in2 = (const float4*)d_in[1];
    float2* out = (float2*)d_out;

    // total input float4s per tensor = B*N*2/4 = 8,388,608; 2 per thread
    const long long total_threads = (long long)B_DIM * N_DIM / 4; // 4,194,304
    const int blocks = (int)(total_threads / THREADS);            // 8192

    prod_cmp_kernel<<<blocks, THREADS>>>(in1, in2, out);
}

// round 12
// speedup vs baseline: 1.0114x; 1.0114x over previous
#include <cuda_runtime.h>

// Prod_cmp: complex multiply + [reals | imags] repack. B=256, N=65536.
// in:  I1, I2 as (B, N, 2) fp32 interleaved complex
// out: (B, 2N) fp32 where out[b, 0..N) = real[b,:], out[b, N..2N) = imag[b,:]
//
// R11 single delta vs R10 (twice-benched best: 51.9-52.0us / 85.4% DRAM at
// 512 threads): block size 512 -> 1024 (4096 CTAs, occ 2), completing the
// block-size axis whose trend (256: 84.8-85.1% -> 512: 85.4%) is the only
// monotone signal of the session. Per-warp access geometry unchanged:
// warp-coalesced 512B-contiguous LDG.128, __stcs coalesced STG.64.

static constexpr int B_DIM = 256;
static constexpr int N_DIM = 65536;            // complex per row
static constexpr int N_SHIFT = 16;             // log2(N_DIM)
static constexpr unsigned N_MASK = N_DIM - 1;

static constexpr int THREADS = 1024;

__global__ void __launch_bounds__(THREADS, 2)
prod_cmp_kernel(const float4* __restrict__ in1,
                const float4* __restrict__ in2,
                float2* __restrict__ out)
{
    const int lane = threadIdx.x & 31;
    const long long gwarp =
        (((long long)blockIdx.x * blockDim.x + threadIdx.x) >> 5);
    const long long warpbase = gwarp * 64;     // first input float4 of this warp
    const long long j0 = warpbase + lane;      // warp-contiguous
    const long long j1 = j0 + 32;              // warp-contiguous

    // Fully coalesced 512B-per-warp loads (each 32B sector fetched once)
    const float4 a0 = in1[j0];
    const float4 a1 = in1[j1];
    const float4 c0 = in2[j0];
    const float4 c1 = in2[j1];

    // float4 j holds complex elements 2j and 2j+1
    const long long cc0 = j0 * 2;                    // first complex of a0
    const unsigned b  = (unsigned)(cc0 >> N_SHIFT);  // row (uniform per warp)
    const unsigned k0 = (unsigned)(cc0 & N_MASK);    // in-row pos of a0 (even)
    const unsigned k1 = k0 + 64;                     // in-row pos of a1 (same row)

    float2 re0, im0, re1, im1;
    re0.x = fmaf(a0.x, c0.x, -a0.y * c0.y);
    im0.x = fmaf(a0.y, c0.x,  a0.x * c0.y);
    re0.y = fmaf(a0.z, c0.z, -a0.w * c0.w);
    im0.y = fmaf(a0.w, c0.z,  a0.z * c0.w);
    re1.x = fmaf(a1.x, c1.x, -a1.y * c1.y);
    im1.x = fmaf(a1.y, c1.x,  a1.x * c1.y);
    re1.y = fmaf(a1.z, c1.z, -a1.w * c1.w);
    im1.y = fmaf(a1.w, c1.z,  a1.z * c1.w);

    // Output row b: 2N floats. As float2 indices:
    //   reals: b*N + k/2,  imags: b*N + N/2 + k/2
    const long long row_f2 = (long long)b * N_DIM;
    __stcs(&out[row_f2 + (k0 >> 1)], re0);
    __stcs(&out[row_f2 + (k1 >> 1)], re1);
    __stcs(&out[row_f2 + (N_DIM >> 1) + (k0 >> 1)], im0);
    __stcs(&out[row_f2 + (N_DIM >> 1) + (k1 >> 1)], im1);
}

extern "C" void kernel_launch(void* const* d_in, const int* in_sizes, int n_in,
                              void* d_out, int out_size)
{
    const float4* in1 = (const float4*)d_in[0];
    const float4* in2 = (const float4*)d_in[1];
    float2* out = (float2*)d_out;

    // total input float4s per tensor = B*N*2/4 = 8,388,608; 2 per thread
    const long long total_threads = (long long)B_DIM * N_DIM / 4; // 4,194,304
    const int blocks = (int)(total_threads / THREADS);            // 4096

    prod_cmp_kernel<<<blocks, THREADS>>>(in1, in2, out);
}